// round 2
// baseline (speedup 1.0000x reference)
#include <cuda_runtime.h>
#include <math.h>

#define BB 4
#define SS 2048
#define DD 512
#define HH 8
#define DKK 64
#define DFF 2048
#define MROWS (BB * SS)   // 8192

// ---------------- scratch (static device globals; no allocations) ----------
__device__ float g_q[MROWS * DD];
__device__ float g_k[MROWS * DD];
__device__ float g_v[MROWS * DD];
__device__ float g_ctx[MROWS * DD];
__device__ float g_attres[MROWS * DD];
__device__ float g_h[MROWS * DD];
__device__ float g_ff[MROWS * DFF];
__device__ float g_ffres[MROWS * DD];

// ---------------- generic SGEMM: C[m,n] = sum_k A[m,k] * W[n,k] (NT) -------
// Epilogues: 0 = none, 1 = +res, 2 = +bias then exact GELU, 3 = +bias +res
template <int EPI>
__global__ __launch_bounds__(256) void gemm_nt(
    const float* __restrict__ A, const float* __restrict__ W,
    const float* __restrict__ bias, const float* __restrict__ res,
    float* __restrict__ C, int M, int N, int K)
{
    __shared__ float As[64][17];
    __shared__ float Bs[64][17];

    const int bm = blockIdx.y * 64;
    const int bn = blockIdx.x * 64;
    const int tid = threadIdx.x;
    const int lr = tid >> 2;            // 0..63 load row
    const int lc = (tid & 3) * 4;       // 0,4,8,12 load col
    const int tx = tid & 15;            // 0..15
    const int ty = tid >> 4;            // 0..15

    float acc[4][4];
#pragma unroll
    for (int i = 0; i < 4; i++)
#pragma unroll
        for (int j = 0; j < 4; j++) acc[i][j] = 0.f;

    for (int k0 = 0; k0 < K; k0 += 16) {
        float4 a = *(const float4*)&A[(size_t)(bm + lr) * K + k0 + lc];
        float4 w = *(const float4*)&W[(size_t)(bn + lr) * K + k0 + lc];
        As[lr][lc + 0] = a.x; As[lr][lc + 1] = a.y;
        As[lr][lc + 2] = a.z; As[lr][lc + 3] = a.w;
        Bs[lr][lc + 0] = w.x; Bs[lr][lc + 1] = w.y;
        Bs[lr][lc + 2] = w.z; Bs[lr][lc + 3] = w.w;
        __syncthreads();
#pragma unroll
        for (int k = 0; k < 16; k++) {
            float ra[4], rb[4];
#pragma unroll
            for (int i = 0; i < 4; i++) ra[i] = As[ty * 4 + i][k];
#pragma unroll
            for (int j = 0; j < 4; j++) rb[j] = Bs[tx * 4 + j][k];
#pragma unroll
            for (int i = 0; i < 4; i++)
#pragma unroll
                for (int j = 0; j < 4; j++) acc[i][j] += ra[i] * rb[j];
        }
        __syncthreads();
    }

#pragma unroll
    for (int i = 0; i < 4; i++) {
#pragma unroll
        for (int j = 0; j < 4; j++) {
            const int m = bm + ty * 4 + i;
            const int n = bn + tx * 4 + j;
            float v = acc[i][j];
            if (EPI == 1) v += res[(size_t)m * N + n];
            if (EPI == 2) {
                v += bias[n];
                v = 0.5f * v * (1.f + erff(v * 0.70710678118654752f));
            }
            if (EPI == 3) v += bias[n] + res[(size_t)m * N + n];
            C[(size_t)m * N + n] = v;
        }
    }
}

// ---------------- flash attention: one thread owns one query row -----------
__global__ __launch_bounds__(128) void attn_k(
    const float* __restrict__ Q, const float* __restrict__ Kt,
    const float* __restrict__ V, const int* __restrict__ mask,
    float* __restrict__ O)
{
    const int bh = blockIdx.x;
    const int b = bh / HH, h = bh % HH;
    const int s = blockIdx.y * 128 + threadIdx.x;
    const int tid = threadIdx.x;

    __shared__ float Ks[32][64];
    __shared__ float Vs[32][64];
    __shared__ float mb[32];

    float q[64];
    {
        const float* qp = Q + (size_t)(b * SS + s) * DD + h * DKK;
#pragma unroll
        for (int d = 0; d < 64; d++) q[d] = qp[d] * 0.125f;  // 1/sqrt(64)
    }
    float o[64];
#pragma unroll
    for (int d = 0; d < 64; d++) o[d] = 0.f;
    float m = -1e30f, l = 0.f;

    for (int t0 = 0; t0 < SS; t0 += 32) {
        // cooperative stage: 32x64 K tile + 32x64 V tile (float4 per thread x4)
#pragma unroll
        for (int i = 0; i < 4; i++) {
            const int idx = tid + i * 128;       // 0..511 float4 slots
            const int r = idx >> 4;              // row 0..31
            const int c = (idx & 15) * 4;        // col 0..60
            const size_t go = (size_t)(b * SS + t0 + r) * DD + h * DKK + c;
            float4 kv = *(const float4*)&Kt[go];
            Ks[r][c + 0] = kv.x; Ks[r][c + 1] = kv.y;
            Ks[r][c + 2] = kv.z; Ks[r][c + 3] = kv.w;
            float4 vv = *(const float4*)&V[go];
            Vs[r][c + 0] = vv.x; Vs[r][c + 1] = vv.y;
            Vs[r][c + 2] = vv.z; Vs[r][c + 3] = vv.w;
        }
        if (tid < 32) mb[tid] = mask[b * SS + t0 + tid] ? 0.f : -100.f;
        __syncthreads();

        float sj[32];
        float cmax = -1e30f;
#pragma unroll
        for (int j = 0; j < 32; j++) {
            float acc = 0.f;
#pragma unroll
            for (int d = 0; d < 64; d++) acc += q[d] * Ks[j][d];
            acc += mb[j];
            sj[j] = acc;
            cmax = fmaxf(cmax, acc);
        }
        const float mnew = fmaxf(m, cmax);
        const float corr = __expf(m - mnew);
        l *= corr;
#pragma unroll
        for (int d = 0; d < 64; d++) o[d] *= corr;
#pragma unroll
        for (int j = 0; j < 32; j++) {
            const float p = __expf(sj[j] - mnew);
            l += p;
#pragma unroll
            for (int d = 0; d < 64; d++) o[d] += p * Vs[j][d];
        }
        m = mnew;
        __syncthreads();
    }

    const float inv = 1.f / l;
    float* op = O + (size_t)(b * SS + s) * DD + h * DKK;
#pragma unroll
    for (int d = 0; d < 64; d++) op[d] = o[d] * inv;
}

// ---------------- layernorm over last dim (D=512), one block per row -------
__global__ __launch_bounds__(256) void layernorm_k(
    const float* __restrict__ in, const float* __restrict__ gamma,
    const float* __restrict__ beta, float* __restrict__ out)
{
    const int row = blockIdx.x;
    const int tid = threadIdx.x;
    const float* xr = in + (size_t)row * DD;

    const float x0 = xr[tid];
    const float x1 = xr[tid + 256];

    __shared__ float wsum[8];
    __shared__ float sval;

    float s = x0 + x1;
#pragma unroll
    for (int off = 16; off; off >>= 1) s += __shfl_xor_sync(0xffffffffu, s, off);
    if ((tid & 31) == 0) wsum[tid >> 5] = s;
    __syncthreads();
    if (tid == 0) {
        float t = 0.f;
#pragma unroll
        for (int i = 0; i < 8; i++) t += wsum[i];
        sval = t * (1.f / DD);
    }
    __syncthreads();
    const float mu = sval;
    __syncthreads();

    const float d0 = x0 - mu, d1 = x1 - mu;
    s = d0 * d0 + d1 * d1;
#pragma unroll
    for (int off = 16; off; off >>= 1) s += __shfl_xor_sync(0xffffffffu, s, off);
    if ((tid & 31) == 0) wsum[tid >> 5] = s;
    __syncthreads();
    if (tid == 0) {
        float t = 0.f;
#pragma unroll
        for (int i = 0; i < 8; i++) t += wsum[i];
        sval = rsqrtf(t * (1.f / DD) + 1e-5f);
    }
    __syncthreads();
    const float rstd = sval;

    out[(size_t)row * DD + tid]       = d0 * rstd * gamma[tid] + beta[tid];
    out[(size_t)row * DD + tid + 256] = d1 * rstd * gamma[tid + 256] + beta[tid + 256];
}

// ---------------- launch --------------------------------------------------
extern "C" void kernel_launch(void* const* d_in, const int* in_sizes, int n_in,
                              void* d_out, int out_size)
{
    const float* x    = (const float*)d_in[0];
    const int*   mask = (const int*)d_in[1];          // bool input lands as int32
    const float* Wq   = (const float*)d_in[2];
    const float* Wk   = (const float*)d_in[3];
    const float* Wv   = (const float*)d_in[4];
    const float* Wp   = (const float*)d_in[5];
    const float* W1   = (const float*)d_in[6];
    const float* b1   = (const float*)d_in[7];
    const float* W2   = (const float*)d_in[8];
    const float* b2   = (const float*)d_in[9];
    const float* ln1g = (const float*)d_in[10];
    const float* ln1b = (const float*)d_in[11];
    const float* ln2g = (const float*)d_in[12];
    const float* ln2b = (const float*)d_in[13];
    float* out = (float*)d_out;

    float *q, *k, *v, *ctx, *attres, *h, *ff, *ffres;
    cudaGetSymbolAddress((void**)&q,      g_q);
    cudaGetSymbolAddress((void**)&k,      g_k);
    cudaGetSymbolAddress((void**)&v,      g_v);
    cudaGetSymbolAddress((void**)&ctx,    g_ctx);
    cudaGetSymbolAddress((void**)&attres, g_attres);
    cudaGetSymbolAddress((void**)&h,      g_h);
    cudaGetSymbolAddress((void**)&ff,     g_ff);
    cudaGetSymbolAddress((void**)&ffres,  g_ffres);

    dim3 g512(DD / 64, MROWS / 64);      // (8, 128)
    dim3 g2048(DFF / 64, MROWS / 64);    // (32, 128)

    // QKV projections
    gemm_nt<0><<<g512, 256>>>(x, Wq, nullptr, nullptr, q, MROWS, DD, DD);
    gemm_nt<0><<<g512, 256>>>(x, Wk, nullptr, nullptr, k, MROWS, DD, DD);
    gemm_nt<0><<<g512, 256>>>(x, Wv, nullptr, nullptr, v, MROWS, DD, DD);

    // attention
    dim3 ga(BB * HH, SS / 128);
    attn_k<<<ga, 128>>>(q, k, v, mask, ctx);

    // output projection + residual, LN1
    gemm_nt<1><<<g512, 256>>>(ctx, Wp, nullptr, x, attres, MROWS, DD, DD);
    layernorm_k<<<MROWS, 256>>>(attres, ln1g, ln1b, h);

    // FFN
    gemm_nt<2><<<g2048, 256>>>(h, W1, b1, nullptr, ff, MROWS, DFF, DD);
    gemm_nt<3><<<g512, 256>>>(ff, W2, b2, h, ffres, MROWS, DD, DFF);
    layernorm_k<<<MROWS, 256>>>(ffres, ln2g, ln2b, out);
}

// round 3
// speedup vs baseline: 1.2319x; 1.2319x over previous
#include <cuda_runtime.h>
#include <math.h>

#define BB 4
#define SS 2048
#define DD 512
#define HH 8
#define DKK 64
#define DFF 2048
#define MROWS (BB * SS)   // 8192

// ---------------- scratch (static device globals; no allocations) ----------
__device__ float g_q[MROWS * DD];
__device__ float g_k[MROWS * DD];
__device__ float g_v[MROWS * DD];
__device__ float g_ctx[MROWS * DD];
__device__ float g_attres[MROWS * DD];
__device__ float g_h[MROWS * DD];
__device__ float g_ff[MROWS * DFF];

// ---------------- SGEMM 128x128 tile, 256 thr, 8x8 micro, double-buffered --
// C[m,n] = sum_k A[m,k] * W[n,k]  (both row-major, NT)
// EPI: 0 none, 1 +res, 2 +bias->GELU, 3 +bias+res
template <int EPI>
__global__ __launch_bounds__(256) void gemm128(
    const float* __restrict__ A, const float* __restrict__ W,
    const float* __restrict__ bias, const float* __restrict__ res,
    float* __restrict__ C, int M, int N, int K)
{
    __shared__ float As[2][8][128];
    __shared__ float Bs[2][8][128];

    const int tid = threadIdx.x;
    const int bm = blockIdx.y * 128;
    const int bn = blockIdx.x * 128;

    const int lr = tid >> 1;          // 0..127 (tile row)
    const int lk = (tid & 1) * 4;     // 0 or 4 (k offset)
    const int tx = tid & 15;          // 0..15
    const int ty = tid >> 4;          // 0..15

    float acc[2][2][4][4];
#pragma unroll
    for (int a = 0; a < 2; a++)
#pragma unroll
        for (int b = 0; b < 2; b++)
#pragma unroll
            for (int i = 0; i < 4; i++)
#pragma unroll
                for (int j = 0; j < 4; j++) acc[a][b][i][j] = 0.f;

    const float* Ap = A + (size_t)(bm + lr) * K + lk;
    const float* Wp = W + (size_t)(bn + lr) * K + lk;

    float4 pa = *(const float4*)Ap;
    float4 pb = *(const float4*)Wp;

    int buf = 0;
    As[0][lk + 0][lr] = pa.x; As[0][lk + 1][lr] = pa.y;
    As[0][lk + 2][lr] = pa.z; As[0][lk + 3][lr] = pa.w;
    Bs[0][lk + 0][lr] = pb.x; Bs[0][lk + 1][lr] = pb.y;
    Bs[0][lk + 2][lr] = pb.z; Bs[0][lk + 3][lr] = pb.w;
    __syncthreads();

    const int ktiles = K >> 3;
    for (int t = 0; t < ktiles; t++) {
        if (t + 1 < ktiles) {
            pa = *(const float4*)(Ap + (t + 1) * 8);
            pb = *(const float4*)(Wp + (t + 1) * 8);
        }
#pragma unroll
        for (int k = 0; k < 8; k++) {
            float a0[4], a1[4], b0[4], b1[4];
            *(float4*)a0 = *(const float4*)&As[buf][k][ty * 4];
            *(float4*)a1 = *(const float4*)&As[buf][k][ty * 4 + 64];
            *(float4*)b0 = *(const float4*)&Bs[buf][k][tx * 4];
            *(float4*)b1 = *(const float4*)&Bs[buf][k][tx * 4 + 64];
#pragma unroll
            for (int i = 0; i < 4; i++)
#pragma unroll
                for (int j = 0; j < 4; j++) {
                    acc[0][0][i][j] += a0[i] * b0[j];
                    acc[0][1][i][j] += a0[i] * b1[j];
                    acc[1][0][i][j] += a1[i] * b0[j];
                    acc[1][1][i][j] += a1[i] * b1[j];
                }
        }
        if (t + 1 < ktiles) {
            buf ^= 1;
            As[buf][lk + 0][lr] = pa.x; As[buf][lk + 1][lr] = pa.y;
            As[buf][lk + 2][lr] = pa.z; As[buf][lk + 3][lr] = pa.w;
            Bs[buf][lk + 0][lr] = pb.x; Bs[buf][lk + 1][lr] = pb.y;
            Bs[buf][lk + 2][lr] = pb.z; Bs[buf][lk + 3][lr] = pb.w;
            __syncthreads();
        }
    }

#pragma unroll
    for (int bi = 0; bi < 2; bi++) {
#pragma unroll
        for (int i = 0; i < 4; i++) {
            const int m = bm + ty * 4 + bi * 64 + i;
#pragma unroll
            for (int bj = 0; bj < 2; bj++) {
                const int n = bn + tx * 4 + bj * 64;
                float4 v = make_float4(acc[bi][bj][i][0], acc[bi][bj][i][1],
                                       acc[bi][bj][i][2], acc[bi][bj][i][3]);
                if (EPI == 1) {
                    float4 r = *(const float4*)&res[(size_t)m * N + n];
                    v.x += r.x; v.y += r.y; v.z += r.z; v.w += r.w;
                }
                if (EPI == 2) {
                    const float4 bb = *(const float4*)&bias[n];
                    v.x += bb.x; v.y += bb.y; v.z += bb.z; v.w += bb.w;
                    v.x = 0.5f * v.x * (1.f + erff(v.x * 0.70710678118654752f));
                    v.y = 0.5f * v.y * (1.f + erff(v.y * 0.70710678118654752f));
                    v.z = 0.5f * v.z * (1.f + erff(v.z * 0.70710678118654752f));
                    v.w = 0.5f * v.w * (1.f + erff(v.w * 0.70710678118654752f));
                }
                if (EPI == 3) {
                    const float4 bb = *(const float4*)&bias[n];
                    float4 r = *(const float4*)&res[(size_t)m * N + n];
                    v.x += bb.x + r.x; v.y += bb.y + r.y;
                    v.z += bb.z + r.z; v.w += bb.w + r.w;
                }
                *(float4*)&C[(size_t)m * N + n] = v;
            }
        }
    }
}

// ---------------- flash attention: one thread owns one query row -----------
__global__ __launch_bounds__(128) void attn_k(
    const float* __restrict__ Q, const float* __restrict__ Kt,
    const float* __restrict__ V, const int* __restrict__ mask,
    float* __restrict__ O)
{
    const int bh = blockIdx.x;
    const int b = bh / HH, h = bh % HH;
    const int s = blockIdx.y * 128 + threadIdx.x;
    const int tid = threadIdx.x;

    __shared__ float4 Ks4[32][16];
    __shared__ float4 Vs4[32][16];
    __shared__ float mb[32];

    float4 q4[16];
    {
        const float4* qp = (const float4*)(Q + (size_t)(b * SS + s) * DD + h * DKK);
#pragma unroll
        for (int d = 0; d < 16; d++) {
            float4 t = qp[d];
            t.x *= 0.125f; t.y *= 0.125f; t.z *= 0.125f; t.w *= 0.125f;
            q4[d] = t;
        }
    }
    float4 o4[16];
#pragma unroll
    for (int d = 0; d < 16; d++) o4[d] = make_float4(0.f, 0.f, 0.f, 0.f);
    float m = -1e30f, l = 0.f;

    for (int t0 = 0; t0 < SS; t0 += 32) {
#pragma unroll
        for (int i = 0; i < 4; i++) {
            const int idx = tid + i * 128;   // 0..511
            const int r = idx >> 4;          // 0..31
            const int c = idx & 15;          // 0..15
            const size_t go = ((size_t)(b * SS + t0 + r) * DD + h * DKK) / 4 + c;
            Ks4[r][c] = ((const float4*)Kt)[go];
            Vs4[r][c] = ((const float4*)V)[go];
        }
        if (tid < 32) mb[tid] = mask[b * SS + t0 + tid] ? 0.f : -100.f;
        __syncthreads();

        float sj[32];
        float cmax = -1e30f;
#pragma unroll
        for (int j = 0; j < 32; j++) {
            float4 a = make_float4(0.f, 0.f, 0.f, 0.f);
#pragma unroll
            for (int d = 0; d < 16; d++) {
                const float4 kj = Ks4[j][d];
                a.x += q4[d].x * kj.x;
                a.y += q4[d].y * kj.y;
                a.z += q4[d].z * kj.z;
                a.w += q4[d].w * kj.w;
            }
            const float sc = (a.x + a.y) + (a.z + a.w) + mb[j];
            sj[j] = sc;
            cmax = fmaxf(cmax, sc);
        }
        const float mnew = fmaxf(m, cmax);
        const float corr = __expf(m - mnew);
        l *= corr;
#pragma unroll
        for (int d = 0; d < 16; d++) {
            o4[d].x *= corr; o4[d].y *= corr; o4[d].z *= corr; o4[d].w *= corr;
        }
#pragma unroll
        for (int j = 0; j < 32; j++) {
            const float p = __expf(sj[j] - mnew);
            l += p;
#pragma unroll
            for (int d = 0; d < 16; d++) {
                const float4 vj = Vs4[j][d];
                o4[d].x += p * vj.x;
                o4[d].y += p * vj.y;
                o4[d].z += p * vj.z;
                o4[d].w += p * vj.w;
            }
        }
        m = mnew;
        __syncthreads();
    }

    const float inv = 1.f / l;
    float4* op = (float4*)(O + (size_t)(b * SS + s) * DD + h * DKK);
#pragma unroll
    for (int d = 0; d < 16; d++) {
        float4 t = o4[d];
        t.x *= inv; t.y *= inv; t.z *= inv; t.w *= inv;
        op[d] = t;
    }
}

// ---------------- layernorm over last dim (D=512), one block per row -------
__global__ __launch_bounds__(256) void layernorm_k(
    const float* __restrict__ in, const float* __restrict__ gamma,
    const float* __restrict__ beta, float* __restrict__ out)
{
    const int row = blockIdx.x;
    const int tid = threadIdx.x;
    const float* xr = in + (size_t)row * DD;

    const float x0 = xr[tid];
    const float x1 = xr[tid + 256];

    __shared__ float wsum[8];
    __shared__ float sval;

    float s = x0 + x1;
#pragma unroll
    for (int off = 16; off; off >>= 1) s += __shfl_xor_sync(0xffffffffu, s, off);
    if ((tid & 31) == 0) wsum[tid >> 5] = s;
    __syncthreads();
    if (tid == 0) {
        float t = 0.f;
#pragma unroll
        for (int i = 0; i < 8; i++) t += wsum[i];
        sval = t * (1.f / DD);
    }
    __syncthreads();
    const float mu = sval;
    __syncthreads();

    const float d0 = x0 - mu, d1 = x1 - mu;
    s = d0 * d0 + d1 * d1;
#pragma unroll
    for (int off = 16; off; off >>= 1) s += __shfl_xor_sync(0xffffffffu, s, off);
    if ((tid & 31) == 0) wsum[tid >> 5] = s;
    __syncthreads();
    if (tid == 0) {
        float t = 0.f;
#pragma unroll
        for (int i = 0; i < 8; i++) t += wsum[i];
        sval = rsqrtf(t * (1.f / DD) + 1e-5f);
    }
    __syncthreads();
    const float rstd = sval;

    out[(size_t)row * DD + tid]       = d0 * rstd * gamma[tid] + beta[tid];
    out[(size_t)row * DD + tid + 256] = d1 * rstd * gamma[tid + 256] + beta[tid + 256];
}

// ---------------- launch --------------------------------------------------
extern "C" void kernel_launch(void* const* d_in, const int* in_sizes, int n_in,
                              void* d_out, int out_size)
{
    const float* x    = (const float*)d_in[0];
    const int*   mask = (const int*)d_in[1];          // bool input lands as int32
    const float* Wq   = (const float*)d_in[2];
    const float* Wk   = (const float*)d_in[3];
    const float* Wv   = (const float*)d_in[4];
    const float* Wp   = (const float*)d_in[5];
    const float* W1   = (const float*)d_in[6];
    const float* b1   = (const float*)d_in[7];
    const float* W2   = (const float*)d_in[8];
    const float* b2   = (const float*)d_in[9];
    const float* ln1g = (const float*)d_in[10];
    const float* ln1b = (const float*)d_in[11];
    const float* ln2g = (const float*)d_in[12];
    const float* ln2b = (const float*)d_in[13];
    float* out = (float*)d_out;

    float *q, *k, *v, *ctx, *attres, *h, *ff;
    cudaGetSymbolAddress((void**)&q,      g_q);
    cudaGetSymbolAddress((void**)&k,      g_k);
    cudaGetSymbolAddress((void**)&v,      g_v);
    cudaGetSymbolAddress((void**)&ctx,    g_ctx);
    cudaGetSymbolAddress((void**)&attres, g_attres);
    cudaGetSymbolAddress((void**)&h,      g_h);
    cudaGetSymbolAddress((void**)&ff,     g_ff);

    dim3 g512(DD / 128, MROWS / 128);     // (4, 64)
    dim3 g2048(DFF / 128, MROWS / 128);   // (16, 64)

    // QKV projections
    gemm128<0><<<g512, 256>>>(x, Wq, nullptr, nullptr, q, MROWS, DD, DD);
    gemm128<0><<<g512, 256>>>(x, Wk, nullptr, nullptr, k, MROWS, DD, DD);
    gemm128<0><<<g512, 256>>>(x, Wv, nullptr, nullptr, v, MROWS, DD, DD);

    // attention
    dim3 ga(BB * HH, SS / 128);
    attn_k<<<ga, 128>>>(q, k, v, mask, ctx);

    // output projection + residual, LN1
    gemm128<1><<<g512, 256>>>(ctx, Wp, nullptr, x, attres, MROWS, DD, DD);
    layernorm_k<<<MROWS, 256>>>(attres, ln1g, ln1b, h);

    // FFN (reuse attres as the ffn2+res buffer)
    gemm128<2><<<g2048, 256>>>(h, W1, b1, nullptr, ff, MROWS, DFF, DD);
    gemm128<3><<<g512, 256>>>(ff, W2, b2, h, attres, MROWS, DD, DFF);
    layernorm_k<<<MROWS, 256>>>(attres, ln2g, ln2b, out);
}

// round 6
// speedup vs baseline: 1.6895x; 1.3715x over previous
#include <cuda_runtime.h>
#include <cuda_bf16.h>
#include <math.h>
#include <stdint.h>

#define BB 4
#define SS 2048
#define DD 512
#define HH 8
#define DKK 64
#define DFF 2048
#define MROWS (BB * SS)   // 8192

// ---------------- scratch (static device globals; no allocations) ----------
__device__ float g_q[MROWS * DD];
__device__ float g_k[MROWS * DD];
__device__ float g_v[MROWS * DD];
__device__ float g_ctx[MROWS * DD];
__device__ float g_attres[MROWS * DD];
__device__ float g_h[MROWS * DD];
__device__ float g_ff[MROWS * DFF];

// ================= mma.sync helpers (sm_80-era PTX, works on sm_103) =======
__device__ __forceinline__ uint32_t smem_u32(const void* p) {
    uint32_t a;
    asm("{ .reg .u64 t; cvta.to.shared.u64 t, %1; cvt.u32.u64 %0, t; }"
        : "=r"(a) : "l"(p));
    return a;
}
__device__ __forceinline__ void ldm_x4(uint32_t& r0, uint32_t& r1,
                                       uint32_t& r2, uint32_t& r3, uint32_t addr) {
    asm volatile("ldmatrix.sync.aligned.m8n8.x4.shared.b16 {%0,%1,%2,%3}, [%4];"
                 : "=r"(r0), "=r"(r1), "=r"(r2), "=r"(r3) : "r"(addr));
}
__device__ __forceinline__ void mma_bf16(float* d, const uint32_t* a,
                                         const uint32_t* b) {
    asm volatile(
        "mma.sync.aligned.m16n8k16.row.col.f32.bf16.bf16.f32 "
        "{%0,%1,%2,%3}, {%4,%5,%6,%7}, {%8,%9}, {%0,%1,%2,%3};"
        : "+f"(d[0]), "+f"(d[1]), "+f"(d[2]), "+f"(d[3])
        : "r"(a[0]), "r"(a[1]), "r"(a[2]), "r"(a[3]), "r"(b[0]), "r"(b[1]));
}
__device__ __forceinline__ uint32_t pack_hi(float a, float b, float& la, float& lb) {
    __nv_bfloat162 h = __floats2bfloat162_rn(a, b);
    la = a - __bfloat162float(h.x);
    lb = b - __bfloat162float(h.y);
    union { __nv_bfloat162 v; uint32_t u; } cv; cv.v = h;
    return cv.u;
}
__device__ __forceinline__ uint32_t pack_bf(float a, float b) {
    __nv_bfloat162 h = __floats2bfloat162_rn(a, b);
    union { __nv_bfloat162 v; uint32_t u; } cv; cv.v = h;
    return cv.u;
}

// ============ HMMA bf16x3 GEMM: C[m,n] = sum_k A[m,k]*W[n,k] ===============
// block tile 128x128, BK=32, 8 warps (2m x 4n), warp tile 64x32
// EPI: 0 none, 1 +res, 2 +bias->GELU, 3 +bias+res
template <int EPI>
__global__ __launch_bounds__(256, 2) void gemm_h(
    const float* __restrict__ A, const float* __restrict__ W,
    const float* __restrict__ bias, const float* __restrict__ res,
    float* __restrict__ C, int M, int N, int K)
{
    // 4 tiles of [128 rows][32 bf16] = 64 B/row, 8 KB each
    __shared__ __align__(16) uint8_t sm[4 * 8192];
    const uint32_t sb = smem_u32(sm);
    const uint32_t AH = 0, AL = 8192, BH = 16384, BL = 24576;

    const int tid = threadIdx.x;
    const int lane = tid & 31;
    const int warp = tid >> 5;
    const int wm = warp >> 2;     // 0..1
    const int wn = warp & 3;      // 0..3
    const int bm = blockIdx.y * 128;
    const int bn = blockIdx.x * 128;

    float acc[4][4][4];
#pragma unroll
    for (int i = 0; i < 4; i++)
#pragma unroll
        for (int j = 0; j < 4; j++)
#pragma unroll
            for (int e = 0; e < 4; e++) acc[i][j][e] = 0.f;

    // ldmatrix per-lane addressing (precompute row-local parts)
    const int arow = lane & 15;            // A: row within 16-row frag
    const int akc  = lane >> 4;            // A: k-chunk select
    const int brow = ((lane >> 4) << 3) + (lane & 7);  // B: row within 16-row pair
    const int bkc  = (lane >> 3) & 1;      // B: k-chunk select
    const uint32_t asw = (uint32_t)(arow & 3);
    const uint32_t bsw = (uint32_t)(brow & 3);

    const int nslab = K >> 5;
    for (int t = 0; t < nslab; t++) {
        const int k0 = t << 5;

        // ---- stage: gmem fp32 -> regs ----
        float4 av[4], wv[4];
#pragma unroll
        for (int i = 0; i < 4; i++) {
            const int idx = tid + i * 256;         // 0..1023
            const int r = idx >> 3, c4 = idx & 7;
            av[i] = *(const float4*)&A[(size_t)(bm + r) * K + k0 + c4 * 4];
            wv[i] = *(const float4*)&W[(size_t)(bn + r) * K + k0 + c4 * 4];
        }
        __syncthreads();   // previous slab's mma reads done

        // ---- convert + swizzled smem store ----
#pragma unroll
        for (int i = 0; i < 4; i++) {
            const int idx = tid + i * 256;
            const int r = idx >> 3, c4 = idx & 7;
            const uint32_t chunk = (uint32_t)(c4 >> 1);
            const uint32_t off = (uint32_t)r * 64 +
                                 ((chunk ^ (uint32_t)(r & 3)) << 4) + (c4 & 1) * 8;
            float lx, ly, lz, lw;
            uint32_t h0 = pack_hi(av[i].x, av[i].y, lx, ly);
            uint32_t h1 = pack_hi(av[i].z, av[i].w, lz, lw);
            *(uint2*)(sm + AH + off) = make_uint2(h0, h1);
            *(uint2*)(sm + AL + off) = make_uint2(pack_bf(lx, ly), pack_bf(lz, lw));
            h0 = pack_hi(wv[i].x, wv[i].y, lx, ly);
            h1 = pack_hi(wv[i].z, wv[i].w, lz, lw);
            *(uint2*)(sm + BH + off) = make_uint2(h0, h1);
            *(uint2*)(sm + BL + off) = make_uint2(pack_bf(lx, ly), pack_bf(lz, lw));
        }
        __syncthreads();

        // ---- mma phase: 2 k-steps of 16 ----
#pragma unroll
        for (int ks = 0; ks < 2; ks++) {
            const uint32_t kca = (uint32_t)(ks * 2 + akc);
            const uint32_t kcb = (uint32_t)(ks * 2 + bkc);

            uint32_t bh[2][4], bl[2][4];
#pragma unroll
            for (int p = 0; p < 2; p++) {
                const uint32_t row = (uint32_t)(wn * 32 + p * 16 + brow);
                const uint32_t off = row * 64 + ((kcb ^ bsw) << 4);
                ldm_x4(bh[p][0], bh[p][1], bh[p][2], bh[p][3], sb + BH + off);
                ldm_x4(bl[p][0], bl[p][1], bl[p][2], bl[p][3], sb + BL + off);
            }
#pragma unroll
            for (int mf = 0; mf < 4; mf++) {
                const uint32_t row = (uint32_t)(wm * 64 + mf * 16 + arow);
                const uint32_t off = row * 64 + ((kca ^ asw) << 4);
                uint32_t ah[4], al[4];
                ldm_x4(ah[0], ah[1], ah[2], ah[3], sb + AH + off);
                ldm_x4(al[0], al[1], al[2], al[3], sb + AL + off);
#pragma unroll
                for (int nf = 0; nf < 4; nf++) {
                    uint32_t* bhp = &bh[nf >> 1][(nf & 1) * 2];
                    uint32_t* blp = &bl[nf >> 1][(nf & 1) * 2];
                    mma_bf16(acc[mf][nf], ah, bhp);
                    mma_bf16(acc[mf][nf], ah, blp);
                    mma_bf16(acc[mf][nf], al, bhp);
                }
            }
        }
    }

    // ---- epilogue ----
#pragma unroll
    for (int mf = 0; mf < 4; mf++) {
#pragma unroll
        for (int nf = 0; nf < 4; nf++) {
            const int r0 = bm + wm * 64 + mf * 16 + (lane >> 2);
            const int cc = bn + wn * 32 + nf * 8 + (lane & 3) * 2;
#pragma unroll
            for (int half = 0; half < 2; half++) {
                const int m = r0 + half * 8;
                float2 v = make_float2(acc[mf][nf][half * 2],
                                       acc[mf][nf][half * 2 + 1]);
                if (EPI == 1) {
                    const float2 r = *(const float2*)&res[(size_t)m * N + cc];
                    v.x += r.x; v.y += r.y;
                }
                if (EPI == 2) {
                    const float2 bb = *(const float2*)&bias[cc];
                    v.x += bb.x; v.y += bb.y;
                    v.x = 0.5f * v.x * (1.f + erff(v.x * 0.70710678118654752f));
                    v.y = 0.5f * v.y * (1.f + erff(v.y * 0.70710678118654752f));
                }
                if (EPI == 3) {
                    const float2 bb = *(const float2*)&bias[cc];
                    const float2 r = *(const float2*)&res[(size_t)m * N + cc];
                    v.x += bb.x + r.x; v.y += bb.y + r.y;
                }
                *(float2*)&C[(size_t)m * N + cc] = v;
            }
        }
    }
}

// ---------------- flash attention: one thread owns one query row -----------
__global__ __launch_bounds__(128) void attn_k(
    const float* __restrict__ Q, const float* __restrict__ Kt,
    const float* __restrict__ V, const int* __restrict__ mask,
    float* __restrict__ O)
{
    const int bh = blockIdx.x;
    const int b = bh / HH, h = bh % HH;
    const int s = blockIdx.y * 128 + threadIdx.x;
    const int tid = threadIdx.x;

    __shared__ float4 Ks4[32][16];
    __shared__ float4 Vs4[32][16];
    __shared__ float mb[32];

    float4 q4[16];
    {
        const float4* qp = (const float4*)(Q + (size_t)(b * SS + s) * DD + h * DKK);
#pragma unroll
        for (int d = 0; d < 16; d++) {
            float4 t = qp[d];
            t.x *= 0.125f; t.y *= 0.125f; t.z *= 0.125f; t.w *= 0.125f;
            q4[d] = t;
        }
    }
    float4 o4[16];
#pragma unroll
    for (int d = 0; d < 16; d++) o4[d] = make_float4(0.f, 0.f, 0.f, 0.f);
    float m = -1e30f, l = 0.f;

    for (int t0 = 0; t0 < SS; t0 += 32) {
#pragma unroll
        for (int i = 0; i < 4; i++) {
            const int idx = tid + i * 128;
            const int r = idx >> 4;
            const int c = idx & 15;
            const size_t go = ((size_t)(b * SS + t0 + r) * DD + h * DKK) / 4 + c;
            Ks4[r][c] = ((const float4*)Kt)[go];
            Vs4[r][c] = ((const float4*)V)[go];
        }
        if (tid < 32) mb[tid] = mask[b * SS + t0 + tid] ? 0.f : -100.f;
        __syncthreads();

        float sj[32];
        float cmax = -1e30f;
#pragma unroll
        for (int j = 0; j < 32; j++) {
            float4 a = make_float4(0.f, 0.f, 0.f, 0.f);
#pragma unroll
            for (int d = 0; d < 16; d++) {
                const float4 kj = Ks4[j][d];
                a.x += q4[d].x * kj.x;
                a.y += q4[d].y * kj.y;
                a.z += q4[d].z * kj.z;
                a.w += q4[d].w * kj.w;
            }
            const float sc = (a.x + a.y) + (a.z + a.w) + mb[j];
            sj[j] = sc;
            cmax = fmaxf(cmax, sc);
        }
        const float mnew = fmaxf(m, cmax);
        const float corr = __expf(m - mnew);
        l *= corr;
#pragma unroll
        for (int d = 0; d < 16; d++) {
            o4[d].x *= corr; o4[d].y *= corr; o4[d].z *= corr; o4[d].w *= corr;
        }
#pragma unroll
        for (int j = 0; j < 32; j++) {
            const float p = __expf(sj[j] - mnew);
            l += p;
#pragma unroll
            for (int d = 0; d < 16; d++) {
                const float4 vj = Vs4[j][d];
                o4[d].x += p * vj.x;
                o4[d].y += p * vj.y;
                o4[d].z += p * vj.z;
                o4[d].w += p * vj.w;
            }
        }
        m = mnew;
        __syncthreads();
    }

    const float inv = 1.f / l;
    float4* op = (float4*)(O + (size_t)(b * SS + s) * DD + h * DKK);
#pragma unroll
    for (int d = 0; d < 16; d++) {
        float4 t = o4[d];
        t.x *= inv; t.y *= inv; t.z *= inv; t.w *= inv;
        op[d] = t;
    }
}

// ---------------- layernorm over last dim (D=512), one block per row -------
__global__ __launch_bounds__(256) void layernorm_k(
    const float* __restrict__ in, const float* __restrict__ gamma,
    const float* __restrict__ beta, float* __restrict__ out)
{
    const int row = blockIdx.x;
    const int tid = threadIdx.x;
    const float* xr = in + (size_t)row * DD;

    const float x0 = xr[tid];
    const float x1 = xr[tid + 256];

    __shared__ float wsum[8];
    __shared__ float sval;

    float s = x0 + x1;
#pragma unroll
    for (int off = 16; off; off >>= 1) s += __shfl_xor_sync(0xffffffffu, s, off);
    if ((tid & 31) == 0) wsum[tid >> 5] = s;
    __syncthreads();
    if (tid == 0) {
        float t = 0.f;
#pragma unroll
        for (int i = 0; i < 8; i++) t += wsum[i];
        sval = t * (1.f / DD);
    }
    __syncthreads();
    const float mu = sval;
    __syncthreads();

    const float d0 = x0 - mu, d1 = x1 - mu;
    s = d0 * d0 + d1 * d1;
#pragma unroll
    for (int off = 16; off; off >>= 1) s += __shfl_xor_sync(0xffffffffu, s, off);
    if ((tid & 31) == 0) wsum[tid >> 5] = s;
    __syncthreads();
    if (tid == 0) {
        float t = 0.f;
#pragma unroll
        for (int i = 0; i < 8; i++) t += wsum[i];
        sval = rsqrtf(t * (1.f / DD) + 1e-5f);
    }
    __syncthreads();
    const float rstd = sval;

    out[(size_t)row * DD + tid]       = d0 * rstd * gamma[tid] + beta[tid];
    out[(size_t)row * DD + tid + 256] = d1 * rstd * gamma[tid + 256] + beta[tid + 256];
}

// ---------------- launch --------------------------------------------------
extern "C" void kernel_launch(void* const* d_in, const int* in_sizes, int n_in,
                              void* d_out, int out_size)
{
    const float* x    = (const float*)d_in[0];
    const int*   mask = (const int*)d_in[1];
    const float* Wq   = (const float*)d_in[2];
    const float* Wk   = (const float*)d_in[3];
    const float* Wv   = (const float*)d_in[4];
    const float* Wp   = (const float*)d_in[5];
    const float* W1   = (const float*)d_in[6];
    const float* b1   = (const float*)d_in[7];
    const float* W2   = (const float*)d_in[8];
    const float* b2   = (const float*)d_in[9];
    const float* ln1g = (const float*)d_in[10];
    const float* ln1b = (const float*)d_in[11];
    const float* ln2g = (const float*)d_in[12];
    const float* ln2b = (const float*)d_in[13];
    float* out = (float*)d_out;

    float *q, *k, *v, *ctx, *attres, *h, *ff;
    cudaGetSymbolAddress((void**)&q,      g_q);
    cudaGetSymbolAddress((void**)&k,      g_k);
    cudaGetSymbolAddress((void**)&v,      g_v);
    cudaGetSymbolAddress((void**)&ctx,    g_ctx);
    cudaGetSymbolAddress((void**)&attres, g_attres);
    cudaGetSymbolAddress((void**)&h,      g_h);
    cudaGetSymbolAddress((void**)&ff,     g_ff);

    dim3 g512(DD / 128, MROWS / 128);     // (4, 64)
    dim3 g2048(DFF / 128, MROWS / 128);   // (16, 64)

    // QKV projections
    gemm_h<0><<<g512, 256>>>(x, Wq, nullptr, nullptr, q, MROWS, DD, DD);
    gemm_h<0><<<g512, 256>>>(x, Wk, nullptr, nullptr, k, MROWS, DD, DD);
    gemm_h<0><<<g512, 256>>>(x, Wv, nullptr, nullptr, v, MROWS, DD, DD);

    // attention
    dim3 ga(BB * HH, SS / 128);
    attn_k<<<ga, 128>>>(q, k, v, mask, ctx);

    // output projection + residual, LN1
    gemm_h<1><<<g512, 256>>>(ctx, Wp, nullptr, x, attres, MROWS, DD, DD);
    layernorm_k<<<MROWS, 256>>>(attres, ln1g, ln1b, h);

    // FFN
    gemm_h<2><<<g2048, 256>>>(h, W1, b1, nullptr, ff, MROWS, DFF, DD);
    gemm_h<3><<<g512, 256>>>(ff, W2, b2, h, attres, MROWS, DD, DFF);
    layernorm_k<<<MROWS, 256>>>(attres, ln2g, ln2b, out);
}

// round 7
// speedup vs baseline: 1.6901x; 1.0004x over previous
#include <cuda_runtime.h>
#include <cuda_bf16.h>
#include <math.h>
#include <stdint.h>

#define BB 4
#define SS 2048
#define DD 512
#define HH 8
#define DKK 64
#define DFF 2048
#define MROWS (BB * SS)   // 8192

// ---------------- scratch (static device globals; no allocations) ----------
__device__ float g_q[MROWS * DD];
__device__ float g_k[MROWS * DD];
__device__ float g_v[MROWS * DD];
__device__ float g_ctx[MROWS * DD];
__device__ float g_attres[MROWS * DD];
__device__ float g_h[MROWS * DD];
__device__ float g_ff[MROWS * DFF];

// ================= mma.sync helpers (sm_80-era PTX, works on sm_103) =======
__device__ __forceinline__ uint32_t smem_u32(const void* p) {
    uint32_t a;
    asm("{ .reg .u64 t; cvta.to.shared.u64 t, %1; cvt.u32.u64 %0, t; }"
        : "=r"(a) : "l"(p));
    return a;
}
__device__ __forceinline__ void ldm_x4(uint32_t& r0, uint32_t& r1,
                                       uint32_t& r2, uint32_t& r3, uint32_t addr) {
    asm volatile("ldmatrix.sync.aligned.m8n8.x4.shared.b16 {%0,%1,%2,%3}, [%4];"
                 : "=r"(r0), "=r"(r1), "=r"(r2), "=r"(r3) : "r"(addr));
}
__device__ __forceinline__ void mma_bf16(float* d, const uint32_t* a,
                                         const uint32_t* b) {
    asm volatile(
        "mma.sync.aligned.m16n8k16.row.col.f32.bf16.bf16.f32 "
        "{%0,%1,%2,%3}, {%4,%5,%6,%7}, {%8,%9}, {%0,%1,%2,%3};"
        : "+f"(d[0]), "+f"(d[1]), "+f"(d[2]), "+f"(d[3])
        : "r"(a[0]), "r"(a[1]), "r"(a[2]), "r"(a[3]), "r"(b[0]), "r"(b[1]));
}
__device__ __forceinline__ uint32_t pack_hi(float a, float b, float& la, float& lb) {
    __nv_bfloat162 h = __floats2bfloat162_rn(a, b);
    la = a - __bfloat162float(h.x);
    lb = b - __bfloat162float(h.y);
    union { __nv_bfloat162 v; uint32_t u; } cv; cv.v = h;
    return cv.u;
}
__device__ __forceinline__ uint32_t pack_bf(float a, float b) {
    __nv_bfloat162 h = __floats2bfloat162_rn(a, b);
    union { __nv_bfloat162 v; uint32_t u; } cv; cv.v = h;
    return cv.u;
}

// ============ HMMA bf16x3 GEMM: C[m,n] = sum_k A[m,k]*W[n,k] ===============
// block tile 128x128, BK=32, 8 warps (2m x 4n), warp tile 64x32
// EPI: 0 none, 1 +res, 2 +bias->GELU, 3 +bias+res
template <int EPI>
__global__ __launch_bounds__(256, 2) void gemm_h(
    const float* __restrict__ A, const float* __restrict__ W,
    const float* __restrict__ bias, const float* __restrict__ res,
    float* __restrict__ C, int M, int N, int K)
{
    // 4 tiles of [128 rows][32 bf16] = 64 B/row, 8 KB each
    __shared__ __align__(16) uint8_t sm[4 * 8192];
    const uint32_t sb = smem_u32(sm);
    const uint32_t AH = 0, AL = 8192, BH = 16384, BL = 24576;

    const int tid = threadIdx.x;
    const int lane = tid & 31;
    const int warp = tid >> 5;
    const int wm = warp >> 2;     // 0..1
    const int wn = warp & 3;      // 0..3
    const int bm = blockIdx.y * 128;
    const int bn = blockIdx.x * 128;

    float acc[4][4][4];
#pragma unroll
    for (int i = 0; i < 4; i++)
#pragma unroll
        for (int j = 0; j < 4; j++)
#pragma unroll
            for (int e = 0; e < 4; e++) acc[i][j][e] = 0.f;

    // ldmatrix per-lane addressing (precompute row-local parts)
    const int arow = lane & 15;            // A: row within 16-row frag
    const int akc  = lane >> 4;            // A: k-chunk select
    const int brow = ((lane >> 4) << 3) + (lane & 7);  // B: row within 16-row pair
    const int bkc  = (lane >> 3) & 1;      // B: k-chunk select
    const uint32_t asw = (uint32_t)(arow & 3);
    const uint32_t bsw = (uint32_t)(brow & 3);

    const int nslab = K >> 5;
    for (int t = 0; t < nslab; t++) {
        const int k0 = t << 5;

        // ---- stage: gmem fp32 -> regs ----
        float4 av[4], wv[4];
#pragma unroll
        for (int i = 0; i < 4; i++) {
            const int idx = tid + i * 256;         // 0..1023
            const int r = idx >> 3, c4 = idx & 7;
            av[i] = *(const float4*)&A[(size_t)(bm + r) * K + k0 + c4 * 4];
            wv[i] = *(const float4*)&W[(size_t)(bn + r) * K + k0 + c4 * 4];
        }
        __syncthreads();   // previous slab's mma reads done

        // ---- convert + swizzled smem store ----
#pragma unroll
        for (int i = 0; i < 4; i++) {
            const int idx = tid + i * 256;
            const int r = idx >> 3, c4 = idx & 7;
            const uint32_t chunk = (uint32_t)(c4 >> 1);
            const uint32_t off = (uint32_t)r * 64 +
                                 ((chunk ^ (uint32_t)(r & 3)) << 4) + (c4 & 1) * 8;
            float lx, ly, lz, lw;
            uint32_t h0 = pack_hi(av[i].x, av[i].y, lx, ly);
            uint32_t h1 = pack_hi(av[i].z, av[i].w, lz, lw);
            *(uint2*)(sm + AH + off) = make_uint2(h0, h1);
            *(uint2*)(sm + AL + off) = make_uint2(pack_bf(lx, ly), pack_bf(lz, lw));
            h0 = pack_hi(wv[i].x, wv[i].y, lx, ly);
            h1 = pack_hi(wv[i].z, wv[i].w, lz, lw);
            *(uint2*)(sm + BH + off) = make_uint2(h0, h1);
            *(uint2*)(sm + BL + off) = make_uint2(pack_bf(lx, ly), pack_bf(lz, lw));
        }
        __syncthreads();

        // ---- mma phase: 2 k-steps of 16 ----
#pragma unroll
        for (int ks = 0; ks < 2; ks++) {
            const uint32_t kca = (uint32_t)(ks * 2 + akc);
            const uint32_t kcb = (uint32_t)(ks * 2 + bkc);

            uint32_t bh[2][4], bl[2][4];
#pragma unroll
            for (int p = 0; p < 2; p++) {
                const uint32_t row = (uint32_t)(wn * 32 + p * 16 + brow);
                const uint32_t off = row * 64 + ((kcb ^ bsw) << 4);
                ldm_x4(bh[p][0], bh[p][1], bh[p][2], bh[p][3], sb + BH + off);
                ldm_x4(bl[p][0], bl[p][1], bl[p][2], bl[p][3], sb + BL + off);
            }
#pragma unroll
            for (int mf = 0; mf < 4; mf++) {
                const uint32_t row = (uint32_t)(wm * 64 + mf * 16 + arow);
                const uint32_t off = row * 64 + ((kca ^ asw) << 4);
                uint32_t ah[4], al[4];
                ldm_x4(ah[0], ah[1], ah[2], ah[3], sb + AH + off);
                ldm_x4(al[0], al[1], al[2], al[3], sb + AL + off);
#pragma unroll
                for (int nf = 0; nf < 4; nf++) {
                    uint32_t* bhp = &bh[nf >> 1][(nf & 1) * 2];
                    uint32_t* blp = &bl[nf >> 1][(nf & 1) * 2];
                    mma_bf16(acc[mf][nf], ah, bhp);
                    mma_bf16(acc[mf][nf], ah, blp);
                    mma_bf16(acc[mf][nf], al, bhp);
                }
            }
        }
    }

    // ---- epilogue ----
#pragma unroll
    for (int mf = 0; mf < 4; mf++) {
#pragma unroll
        for (int nf = 0; nf < 4; nf++) {
            const int r0 = bm + wm * 64 + mf * 16 + (lane >> 2);
            const int cc = bn + wn * 32 + nf * 8 + (lane & 3) * 2;
#pragma unroll
            for (int half = 0; half < 2; half++) {
                const int m = r0 + half * 8;
                float2 v = make_float2(acc[mf][nf][half * 2],
                                       acc[mf][nf][half * 2 + 1]);
                if (EPI == 1) {
                    const float2 r = *(const float2*)&res[(size_t)m * N + cc];
                    v.x += r.x; v.y += r.y;
                }
                if (EPI == 2) {
                    const float2 bb = *(const float2*)&bias[cc];
                    v.x += bb.x; v.y += bb.y;
                    v.x = 0.5f * v.x * (1.f + erff(v.x * 0.70710678118654752f));
                    v.y = 0.5f * v.y * (1.f + erff(v.y * 0.70710678118654752f));
                }
                if (EPI == 3) {
                    const float2 bb = *(const float2*)&bias[cc];
                    const float2 r = *(const float2*)&res[(size_t)m * N + cc];
                    v.x += bb.x + r.x; v.y += bb.y + r.y;
                }
                *(float2*)&C[(size_t)m * N + cc] = v;
            }
        }
    }
}

// ---------------- flash attention: one thread owns one query row -----------
__global__ __launch_bounds__(128) void attn_k(
    const float* __restrict__ Q, const float* __restrict__ Kt,
    const float* __restrict__ V, const int* __restrict__ mask,
    float* __restrict__ O)
{
    const int bh = blockIdx.x;
    const int b = bh / HH, h = bh % HH;
    const int s = blockIdx.y * 128 + threadIdx.x;
    const int tid = threadIdx.x;

    __shared__ float4 Ks4[32][16];
    __shared__ float4 Vs4[32][16];
    __shared__ float mb[32];

    float4 q4[16];
    {
        const float4* qp = (const float4*)(Q + (size_t)(b * SS + s) * DD + h * DKK);
#pragma unroll
        for (int d = 0; d < 16; d++) {
            float4 t = qp[d];
            t.x *= 0.125f; t.y *= 0.125f; t.z *= 0.125f; t.w *= 0.125f;
            q4[d] = t;
        }
    }
    float4 o4[16];
#pragma unroll
    for (int d = 0; d < 16; d++) o4[d] = make_float4(0.f, 0.f, 0.f, 0.f);
    float m = -1e30f, l = 0.f;

    for (int t0 = 0; t0 < SS; t0 += 32) {
#pragma unroll
        for (int i = 0; i < 4; i++) {
            const int idx = tid + i * 128;
            const int r = idx >> 4;
            const int c = idx & 15;
            const size_t go = ((size_t)(b * SS + t0 + r) * DD + h * DKK) / 4 + c;
            Ks4[r][c] = ((const float4*)Kt)[go];
            Vs4[r][c] = ((const float4*)V)[go];
        }
        if (tid < 32) mb[tid] = mask[b * SS + t0 + tid] ? 0.f : -100.f;
        __syncthreads();

        float sj[32];
        float cmax = -1e30f;
#pragma unroll
        for (int j = 0; j < 32; j++) {
            float4 a = make_float4(0.f, 0.f, 0.f, 0.f);
#pragma unroll
            for (int d = 0; d < 16; d++) {
                const float4 kj = Ks4[j][d];
                a.x += q4[d].x * kj.x;
                a.y += q4[d].y * kj.y;
                a.z += q4[d].z * kj.z;
                a.w += q4[d].w * kj.w;
            }
            const float sc = (a.x + a.y) + (a.z + a.w) + mb[j];
            sj[j] = sc;
            cmax = fmaxf(cmax, sc);
        }
        const float mnew = fmaxf(m, cmax);
        const float corr = __expf(m - mnew);
        l *= corr;
#pragma unroll
        for (int d = 0; d < 16; d++) {
            o4[d].x *= corr; o4[d].y *= corr; o4[d].z *= corr; o4[d].w *= corr;
        }
#pragma unroll
        for (int j = 0; j < 32; j++) {
            const float p = __expf(sj[j] - mnew);
            l += p;
#pragma unroll
            for (int d = 0; d < 16; d++) {
                const float4 vj = Vs4[j][d];
                o4[d].x += p * vj.x;
                o4[d].y += p * vj.y;
                o4[d].z += p * vj.z;
                o4[d].w += p * vj.w;
            }
        }
        m = mnew;
        __syncthreads();
    }

    const float inv = 1.f / l;
    float4* op = (float4*)(O + (size_t)(b * SS + s) * DD + h * DKK);
#pragma unroll
    for (int d = 0; d < 16; d++) {
        float4 t = o4[d];
        t.x *= inv; t.y *= inv; t.z *= inv; t.w *= inv;
        op[d] = t;
    }
}

// ---------------- layernorm over last dim (D=512), one block per row -------
__global__ __launch_bounds__(256) void layernorm_k(
    const float* __restrict__ in, const float* __restrict__ gamma,
    const float* __restrict__ beta, float* __restrict__ out)
{
    const int row = blockIdx.x;
    const int tid = threadIdx.x;
    const float* xr = in + (size_t)row * DD;

    const float x0 = xr[tid];
    const float x1 = xr[tid + 256];

    __shared__ float wsum[8];
    __shared__ float sval;

    float s = x0 + x1;
#pragma unroll
    for (int off = 16; off; off >>= 1) s += __shfl_xor_sync(0xffffffffu, s, off);
    if ((tid & 31) == 0) wsum[tid >> 5] = s;
    __syncthreads();
    if (tid == 0) {
        float t = 0.f;
#pragma unroll
        for (int i = 0; i < 8; i++) t += wsum[i];
        sval = t * (1.f / DD);
    }
    __syncthreads();
    const float mu = sval;
    __syncthreads();

    const float d0 = x0 - mu, d1 = x1 - mu;
    s = d0 * d0 + d1 * d1;
#pragma unroll
    for (int off = 16; off; off >>= 1) s += __shfl_xor_sync(0xffffffffu, s, off);
    if ((tid & 31) == 0) wsum[tid >> 5] = s;
    __syncthreads();
    if (tid == 0) {
        float t = 0.f;
#pragma unroll
        for (int i = 0; i < 8; i++) t += wsum[i];
        sval = rsqrtf(t * (1.f / DD) + 1e-5f);
    }
    __syncthreads();
    const float rstd = sval;

    out[(size_t)row * DD + tid]       = d0 * rstd * gamma[tid] + beta[tid];
    out[(size_t)row * DD + tid + 256] = d1 * rstd * gamma[tid + 256] + beta[tid + 256];
}

// ---------------- launch --------------------------------------------------
extern "C" void kernel_launch(void* const* d_in, const int* in_sizes, int n_in,
                              void* d_out, int out_size)
{
    const float* x    = (const float*)d_in[0];
    const int*   mask = (const int*)d_in[1];
    const float* Wq   = (const float*)d_in[2];
    const float* Wk   = (const float*)d_in[3];
    const float* Wv   = (const float*)d_in[4];
    const float* Wp   = (const float*)d_in[5];
    const float* W1   = (const float*)d_in[6];
    const float* b1   = (const float*)d_in[7];
    const float* W2   = (const float*)d_in[8];
    const float* b2   = (const float*)d_in[9];
    const float* ln1g = (const float*)d_in[10];
    const float* ln1b = (const float*)d_in[11];
    const float* ln2g = (const float*)d_in[12];
    const float* ln2b = (const float*)d_in[13];
    float* out = (float*)d_out;

    float *q, *k, *v, *ctx, *attres, *h, *ff;
    cudaGetSymbolAddress((void**)&q,      g_q);
    cudaGetSymbolAddress((void**)&k,      g_k);
    cudaGetSymbolAddress((void**)&v,      g_v);
    cudaGetSymbolAddress((void**)&ctx,    g_ctx);
    cudaGetSymbolAddress((void**)&attres, g_attres);
    cudaGetSymbolAddress((void**)&h,      g_h);
    cudaGetSymbolAddress((void**)&ff,     g_ff);

    dim3 g512(DD / 128, MROWS / 128);     // (4, 64)
    dim3 g2048(DFF / 128, MROWS / 128);   // (16, 64)

    // QKV projections
    gemm_h<0><<<g512, 256>>>(x, Wq, nullptr, nullptr, q, MROWS, DD, DD);
    gemm_h<0><<<g512, 256>>>(x, Wk, nullptr, nullptr, k, MROWS, DD, DD);
    gemm_h<0><<<g512, 256>>>(x, Wv, nullptr, nullptr, v, MROWS, DD, DD);

    // attention
    dim3 ga(BB * HH, SS / 128);
    attn_k<<<ga, 128>>>(q, k, v, mask, ctx);

    // output projection + residual, LN1
    gemm_h<1><<<g512, 256>>>(ctx, Wp, nullptr, x, attres, MROWS, DD, DD);
    layernorm_k<<<MROWS, 256>>>(attres, ln1g, ln1b, h);

    // FFN
    gemm_h<2><<<g2048, 256>>>(h, W1, b1, nullptr, ff, MROWS, DFF, DD);
    gemm_h<3><<<g512, 256>>>(ff, W2, b2, h, attres, MROWS, DD, DFF);
    layernorm_k<<<MROWS, 256>>>(attres, ln2g, ln2b, out);
}

// round 8
// speedup vs baseline: 3.2618x; 1.9299x over previous
#include <cuda_runtime.h>
#include <cuda_bf16.h>
#include <math.h>
#include <stdint.h>

#define BB 4
#define SS 2048
#define DD 512
#define HH 8
#define DKK 64
#define DFF 2048
#define MROWS (BB * SS)   // 8192

// ---------------- scratch (static device globals; no allocations) ----------
__device__ float g_q[MROWS * DD];
__device__ float g_k[MROWS * DD];
__device__ float g_v[MROWS * DD];
__device__ float g_ctx[MROWS * DD];
__device__ float g_attres[MROWS * DD];
__device__ float g_h[MROWS * DD];
__device__ float g_ff[MROWS * DFF];

// ================= mma.sync helpers (sm_80-era PTX, works on sm_103) =======
__device__ __forceinline__ uint32_t smem_u32(const void* p) {
    uint32_t a;
    asm("{ .reg .u64 t; cvta.to.shared.u64 t, %1; cvt.u32.u64 %0, t; }"
        : "=r"(a) : "l"(p));
    return a;
}
__device__ __forceinline__ void ldm_x4(uint32_t& r0, uint32_t& r1,
                                       uint32_t& r2, uint32_t& r3, uint32_t addr) {
    asm volatile("ldmatrix.sync.aligned.m8n8.x4.shared.b16 {%0,%1,%2,%3}, [%4];"
                 : "=r"(r0), "=r"(r1), "=r"(r2), "=r"(r3) : "r"(addr));
}
__device__ __forceinline__ void ldm_x4_t(uint32_t& r0, uint32_t& r1,
                                         uint32_t& r2, uint32_t& r3, uint32_t addr) {
    asm volatile("ldmatrix.sync.aligned.m8n8.x4.trans.shared.b16 {%0,%1,%2,%3}, [%4];"
                 : "=r"(r0), "=r"(r1), "=r"(r2), "=r"(r3) : "r"(addr));
}
__device__ __forceinline__ void mma_bf16(float* d, const uint32_t* a,
                                         const uint32_t* b) {
    asm volatile(
        "mma.sync.aligned.m16n8k16.row.col.f32.bf16.bf16.f32 "
        "{%0,%1,%2,%3}, {%4,%5,%6,%7}, {%8,%9}, {%0,%1,%2,%3};"
        : "+f"(d[0]), "+f"(d[1]), "+f"(d[2]), "+f"(d[3])
        : "r"(a[0]), "r"(a[1]), "r"(a[2]), "r"(a[3]), "r"(b[0]), "r"(b[1]));
}
__device__ __forceinline__ uint32_t pack_hi(float a, float b, float& la, float& lb) {
    __nv_bfloat162 h = __floats2bfloat162_rn(a, b);
    la = a - __bfloat162float(h.x);
    lb = b - __bfloat162float(h.y);
    union { __nv_bfloat162 v; uint32_t u; } cv; cv.v = h;
    return cv.u;
}
__device__ __forceinline__ uint32_t pack_bf(float a, float b) {
    __nv_bfloat162 h = __floats2bfloat162_rn(a, b);
    union { __nv_bfloat162 v; uint32_t u; } cv; cv.v = h;
    return cv.u;
}
// swizzled offset for 128B rows (64 bf16): 8 chunks of 16B, XOR row&7
__device__ __forceinline__ uint32_t offsw(uint32_t row, uint32_t chunk) {
    return row * 128u + ((chunk ^ (row & 7u)) << 4);
}

// ============ HMMA bf16x3 GEMM: C[m,n] = sum_k A[m,k]*W[n,k] ===============
// block tile 128x128, BK=32, 8 warps (2m x 4n), warp tile 64x32
// EPI: 0 none, 1 +res, 2 +bias->GELU, 3 +bias+res
template <int EPI>
__global__ __launch_bounds__(256, 2) void gemm_h(
    const float* __restrict__ A, const float* __restrict__ W,
    const float* __restrict__ bias, const float* __restrict__ res,
    float* __restrict__ C, int M, int N, int K)
{
    __shared__ __align__(16) uint8_t sm[4 * 8192];
    const uint32_t sb = smem_u32(sm);
    const uint32_t AH = 0, AL = 8192, BH = 16384, BL = 24576;

    const int tid = threadIdx.x;
    const int lane = tid & 31;
    const int warp = tid >> 5;
    const int wm = warp >> 2;
    const int wn = warp & 3;
    const int bm = blockIdx.y * 128;
    const int bn = blockIdx.x * 128;

    float acc[4][4][4];
#pragma unroll
    for (int i = 0; i < 4; i++)
#pragma unroll
        for (int j = 0; j < 4; j++)
#pragma unroll
            for (int e = 0; e < 4; e++) acc[i][j][e] = 0.f;

    const int arow = lane & 15;
    const int akc  = lane >> 4;
    const int brow = ((lane >> 4) << 3) + (lane & 7);
    const int bkc  = (lane >> 3) & 1;
    const uint32_t asw = (uint32_t)(arow & 3);
    const uint32_t bsw = (uint32_t)(brow & 3);

    const int nslab = K >> 5;
    for (int t = 0; t < nslab; t++) {
        const int k0 = t << 5;

        float4 av[4], wv[4];
#pragma unroll
        for (int i = 0; i < 4; i++) {
            const int idx = tid + i * 256;
            const int r = idx >> 3, c4 = idx & 7;
            av[i] = *(const float4*)&A[(size_t)(bm + r) * K + k0 + c4 * 4];
            wv[i] = *(const float4*)&W[(size_t)(bn + r) * K + k0 + c4 * 4];
        }
        __syncthreads();

#pragma unroll
        for (int i = 0; i < 4; i++) {
            const int idx = tid + i * 256;
            const int r = idx >> 3, c4 = idx & 7;
            const uint32_t chunk = (uint32_t)(c4 >> 1);
            const uint32_t off = (uint32_t)r * 64 +
                                 ((chunk ^ (uint32_t)(r & 3)) << 4) + (c4 & 1) * 8;
            float lx, ly, lz, lw;
            uint32_t h0 = pack_hi(av[i].x, av[i].y, lx, ly);
            uint32_t h1 = pack_hi(av[i].z, av[i].w, lz, lw);
            *(uint2*)(sm + AH + off) = make_uint2(h0, h1);
            *(uint2*)(sm + AL + off) = make_uint2(pack_bf(lx, ly), pack_bf(lz, lw));
            h0 = pack_hi(wv[i].x, wv[i].y, lx, ly);
            h1 = pack_hi(wv[i].z, wv[i].w, lz, lw);
            *(uint2*)(sm + BH + off) = make_uint2(h0, h1);
            *(uint2*)(sm + BL + off) = make_uint2(pack_bf(lx, ly), pack_bf(lz, lw));
        }
        __syncthreads();

#pragma unroll
        for (int ks = 0; ks < 2; ks++) {
            const uint32_t kca = (uint32_t)(ks * 2 + akc);
            const uint32_t kcb = (uint32_t)(ks * 2 + bkc);

            uint32_t bh[2][4], bl[2][4];
#pragma unroll
            for (int p = 0; p < 2; p++) {
                const uint32_t row = (uint32_t)(wn * 32 + p * 16 + brow);
                const uint32_t off = row * 64 + ((kcb ^ bsw) << 4);
                ldm_x4(bh[p][0], bh[p][1], bh[p][2], bh[p][3], sb + BH + off);
                ldm_x4(bl[p][0], bl[p][1], bl[p][2], bl[p][3], sb + BL + off);
            }
#pragma unroll
            for (int mf = 0; mf < 4; mf++) {
                const uint32_t row = (uint32_t)(wm * 64 + mf * 16 + arow);
                const uint32_t off = row * 64 + ((kca ^ asw) << 4);
                uint32_t ah[4], al[4];
                ldm_x4(ah[0], ah[1], ah[2], ah[3], sb + AH + off);
                ldm_x4(al[0], al[1], al[2], al[3], sb + AL + off);
#pragma unroll
                for (int nf = 0; nf < 4; nf++) {
                    uint32_t* bhp = &bh[nf >> 1][(nf & 1) * 2];
                    uint32_t* blp = &bl[nf >> 1][(nf & 1) * 2];
                    mma_bf16(acc[mf][nf], ah, bhp);
                    mma_bf16(acc[mf][nf], ah, blp);
                    mma_bf16(acc[mf][nf], al, bhp);
                }
            }
        }
    }

#pragma unroll
    for (int mf = 0; mf < 4; mf++) {
#pragma unroll
        for (int nf = 0; nf < 4; nf++) {
            const int r0 = bm + wm * 64 + mf * 16 + (lane >> 2);
            const int cc = bn + wn * 32 + nf * 8 + (lane & 3) * 2;
#pragma unroll
            for (int half = 0; half < 2; half++) {
                const int m = r0 + half * 8;
                float2 v = make_float2(acc[mf][nf][half * 2],
                                       acc[mf][nf][half * 2 + 1]);
                if (EPI == 1) {
                    const float2 r = *(const float2*)&res[(size_t)m * N + cc];
                    v.x += r.x; v.y += r.y;
                }
                if (EPI == 2) {
                    const float2 bb = *(const float2*)&bias[cc];
                    v.x += bb.x; v.y += bb.y;
                    v.x = 0.5f * v.x * (1.f + erff(v.x * 0.70710678118654752f));
                    v.y = 0.5f * v.y * (1.f + erff(v.y * 0.70710678118654752f));
                }
                if (EPI == 3) {
                    const float2 bb = *(const float2*)&bias[cc];
                    const float2 r = *(const float2*)&res[(size_t)m * N + cc];
                    v.x += bb.x + r.x; v.y += bb.y + r.y;
                }
                *(float2*)&C[(size_t)m * N + cc] = v;
            }
        }
    }
}

// ============ HMMA bf16x3 flash attention ==================================
// CTA: 128 query rows of one (b,h). 8 warps x 16-row tiles. 64-key chunks.
__global__ __launch_bounds__(256) void attn_mma(
    const float* __restrict__ Q, const float* __restrict__ Kg,
    const float* __restrict__ Vg, const int* __restrict__ mask,
    float* __restrict__ O)
{
    __shared__ __align__(16) uint8_t sm[32768 + 256];
    const uint32_t sb = smem_u32(sm);
    const uint32_t KH = 0, KL = 8192, VH = 16384, VL = 24576, MB = 32768;
    float* mbf = (float*)(sm + MB);

    const int tid = threadIdx.x;
    const int lane = tid & 31;
    const int warp = tid >> 5;
    const int bh = blockIdx.x;
    const int b = bh / HH, h = bh % HH;
    const int bm = blockIdx.y * 128;

    // ---- stage Q (scaled by 1/8) into smem hi/lo, then ldmatrix to regs ----
#pragma unroll
    for (int i = 0; i < 4; i++) {
        const int slot = tid + i * 256;        // 0..1023 = 128 rows x 8 chunks
        const int r = slot >> 3, ch = slot & 7;
        const float4 f0 = *(const float4*)&Q[(size_t)(b * SS + bm + r) * DD + h * DKK + ch * 8];
        const float4 f1 = *(const float4*)&Q[(size_t)(b * SS + bm + r) * DD + h * DKK + ch * 8 + 4];
        float la, lb, lc, ld, le, lf, lg, lh;
        uint4 hi, lo;
        hi.x = pack_hi(f0.x * 0.125f, f0.y * 0.125f, la, lb);
        hi.y = pack_hi(f0.z * 0.125f, f0.w * 0.125f, lc, ld);
        hi.z = pack_hi(f1.x * 0.125f, f1.y * 0.125f, le, lf);
        hi.w = pack_hi(f1.z * 0.125f, f1.w * 0.125f, lg, lh);
        lo.x = pack_bf(la, lb); lo.y = pack_bf(lc, ld);
        lo.z = pack_bf(le, lf); lo.w = pack_bf(lg, lh);
        const uint32_t off = offsw((uint32_t)r, (uint32_t)ch);
        *(uint4*)(sm + off) = hi;              // hi in [KH..KL+8K) region (16KB)
        *(uint4*)(sm + 16384 + off) = lo;      // lo in [VH..) region (16KB)
    }
    __syncthreads();

    const int arow = lane & 15;
    const int akc  = lane >> 4;
    uint32_t Qh[4][4], Ql[4][4];
    {
        const uint32_t row = (uint32_t)(warp * 16 + arow);
#pragma unroll
        for (int kc = 0; kc < 4; kc++) {
            const uint32_t off = offsw(row, (uint32_t)(kc * 2 + akc));
            ldm_x4(Qh[kc][0], Qh[kc][1], Qh[kc][2], Qh[kc][3], sb + off);
            ldm_x4(Ql[kc][0], Ql[kc][1], Ql[kc][2], Ql[kc][3], sb + 16384 + off);
        }
    }
    __syncthreads();

    const int brow = ((lane >> 4) << 3) + (lane & 7);
    const int bkc  = (lane >> 3) & 1;
    const int vkey = lane & 15;         // trans-ldm key row
    const int vch  = lane >> 4;         // trans-ldm dv-chunk offset

    float S[8][4];
    float Ofr[8][4];
#pragma unroll
    for (int nf = 0; nf < 8; nf++)
#pragma unroll
        for (int e = 0; e < 4; e++) Ofr[nf][e] = 0.f;
    float m0 = -1e30f, m1 = -1e30f, l0 = 0.f, l1 = 0.f;

    for (int t0 = 0; t0 < SS; t0 += 64) {
        // ---- load K,V chunk -> hi/lo smem ----
#pragma unroll
        for (int i = 0; i < 2; i++) {
            const int slot = tid + i * 256;    // 0..511 = 64 rows x 8 chunks
            const int r = slot >> 3, ch = slot & 7;
            const size_t gbase = (size_t)(b * SS + t0 + r) * DD + h * DKK + ch * 8;
            const uint32_t off = offsw((uint32_t)r, (uint32_t)ch);
            {
                const float4 f0 = *(const float4*)&Kg[gbase];
                const float4 f1 = *(const float4*)&Kg[gbase + 4];
                float la, lb, lc, ld, le, lf, lg, lh;
                uint4 hi, lo;
                hi.x = pack_hi(f0.x, f0.y, la, lb);
                hi.y = pack_hi(f0.z, f0.w, lc, ld);
                hi.z = pack_hi(f1.x, f1.y, le, lf);
                hi.w = pack_hi(f1.z, f1.w, lg, lh);
                lo.x = pack_bf(la, lb); lo.y = pack_bf(lc, ld);
                lo.z = pack_bf(le, lf); lo.w = pack_bf(lg, lh);
                *(uint4*)(sm + KH + off) = hi;
                *(uint4*)(sm + KL + off) = lo;
            }
            {
                const float4 f0 = *(const float4*)&Vg[gbase];
                const float4 f1 = *(const float4*)&Vg[gbase + 4];
                float la, lb, lc, ld, le, lf, lg, lh;
                uint4 hi, lo;
                hi.x = pack_hi(f0.x, f0.y, la, lb);
                hi.y = pack_hi(f0.z, f0.w, lc, ld);
                hi.z = pack_hi(f1.x, f1.y, le, lf);
                hi.w = pack_hi(f1.z, f1.w, lg, lh);
                lo.x = pack_bf(la, lb); lo.y = pack_bf(lc, ld);
                lo.z = pack_bf(le, lf); lo.w = pack_bf(lg, lh);
                *(uint4*)(sm + VH + off) = hi;
                *(uint4*)(sm + VL + off) = lo;
            }
        }
        if (tid < 64) mbf[tid] = mask[b * SS + t0 + tid] ? 0.f : -100.f;
        __syncthreads();

        // ---- S = Q K^T (bf16x3) ----
#pragma unroll
        for (int nf = 0; nf < 8; nf++)
#pragma unroll
            for (int e = 0; e < 4; e++) S[nf][e] = 0.f;

#pragma unroll
        for (int p = 0; p < 4; p++) {          // 16-key group
#pragma unroll
            for (int kc = 0; kc < 4; kc++) {
                const uint32_t row = (uint32_t)(p * 16 + brow);
                const uint32_t off = offsw(row, (uint32_t)(kc * 2 + bkc));
                uint32_t kh[4], kl[4];
                ldm_x4(kh[0], kh[1], kh[2], kh[3], sb + KH + off);
                ldm_x4(kl[0], kl[1], kl[2], kl[3], sb + KL + off);
                mma_bf16(S[p * 2],     Qh[kc], &kh[0]);
                mma_bf16(S[p * 2 + 1], Qh[kc], &kh[2]);
                mma_bf16(S[p * 2],     Qh[kc], &kl[0]);
                mma_bf16(S[p * 2 + 1], Qh[kc], &kl[2]);
                mma_bf16(S[p * 2],     Ql[kc], &kh[0]);
                mma_bf16(S[p * 2 + 1], Ql[kc], &kh[2]);
            }
        }

        // ---- mask + online softmax ----
        float cm0 = -1e30f, cm1 = -1e30f;
#pragma unroll
        for (int nf = 0; nf < 8; nf++) {
            const float2 mv = *(const float2*)&mbf[nf * 8 + (lane & 3) * 2];
            S[nf][0] += mv.x; S[nf][1] += mv.y;
            S[nf][2] += mv.x; S[nf][3] += mv.y;
            cm0 = fmaxf(cm0, fmaxf(S[nf][0], S[nf][1]));
            cm1 = fmaxf(cm1, fmaxf(S[nf][2], S[nf][3]));
        }
        cm0 = fmaxf(cm0, __shfl_xor_sync(0xffffffffu, cm0, 1));
        cm0 = fmaxf(cm0, __shfl_xor_sync(0xffffffffu, cm0, 2));
        cm1 = fmaxf(cm1, __shfl_xor_sync(0xffffffffu, cm1, 1));
        cm1 = fmaxf(cm1, __shfl_xor_sync(0xffffffffu, cm1, 2));

        const float mn0 = fmaxf(m0, cm0);
        const float mn1 = fmaxf(m1, cm1);
        const float c0 = __expf(m0 - mn0);
        const float c1 = __expf(m1 - mn1);
        m0 = mn0; m1 = mn1;
        l0 *= c0; l1 *= c1;
#pragma unroll
        for (int nf = 0; nf < 8; nf++) {
            Ofr[nf][0] *= c0; Ofr[nf][1] *= c0;
            Ofr[nf][2] *= c1; Ofr[nf][3] *= c1;
        }
#pragma unroll
        for (int nf = 0; nf < 8; nf++) {
            S[nf][0] = __expf(S[nf][0] - mn0);
            S[nf][1] = __expf(S[nf][1] - mn0);
            S[nf][2] = __expf(S[nf][2] - mn1);
            S[nf][3] = __expf(S[nf][3] - mn1);
            l0 += S[nf][0] + S[nf][1];
            l1 += S[nf][2] + S[nf][3];
        }

        // ---- O += P V (bf16x3), P from score frags ----
#pragma unroll
        for (int kcp = 0; kcp < 4; kcp++) {
            uint32_t Ah[4], Al[4];
            float ra, rb;
            Ah[0] = pack_hi(S[kcp * 2][0],     S[kcp * 2][1],     ra, rb); Al[0] = pack_bf(ra, rb);
            Ah[1] = pack_hi(S[kcp * 2][2],     S[kcp * 2][3],     ra, rb); Al[1] = pack_bf(ra, rb);
            Ah[2] = pack_hi(S[kcp * 2 + 1][0], S[kcp * 2 + 1][1], ra, rb); Al[2] = pack_bf(ra, rb);
            Ah[3] = pack_hi(S[kcp * 2 + 1][2], S[kcp * 2 + 1][3], ra, rb); Al[3] = pack_bf(ra, rb);
#pragma unroll
            for (int vv = 0; vv < 4; vv++) {
                const uint32_t off = offsw((uint32_t)(kcp * 16 + vkey),
                                           (uint32_t)(vv * 2 + vch));
                uint32_t vh[4], vl[4];
                ldm_x4_t(vh[0], vh[1], vh[2], vh[3], sb + VH + off);
                ldm_x4_t(vl[0], vl[1], vl[2], vl[3], sb + VL + off);
                mma_bf16(Ofr[vv * 2],     Ah, &vh[0]);
                mma_bf16(Ofr[vv * 2 + 1], Ah, &vh[2]);
                mma_bf16(Ofr[vv * 2],     Ah, &vl[0]);
                mma_bf16(Ofr[vv * 2 + 1], Ah, &vl[2]);
                mma_bf16(Ofr[vv * 2],     Al, &vh[0]);
                mma_bf16(Ofr[vv * 2 + 1], Al, &vh[2]);
            }
        }
        __syncthreads();
    }

    // ---- finalize ----
    l0 += __shfl_xor_sync(0xffffffffu, l0, 1);
    l0 += __shfl_xor_sync(0xffffffffu, l0, 2);
    l1 += __shfl_xor_sync(0xffffffffu, l1, 1);
    l1 += __shfl_xor_sync(0xffffffffu, l1, 2);
    const float i0 = 1.f / l0, i1 = 1.f / l1;

    const int r0 = b * SS + bm + warp * 16 + (lane >> 2);
#pragma unroll
    for (int nf = 0; nf < 8; nf++) {
        const int col = h * DKK + nf * 8 + (lane & 3) * 2;
        *(float2*)&O[(size_t)r0 * DD + col] =
            make_float2(Ofr[nf][0] * i0, Ofr[nf][1] * i0);
        *(float2*)&O[(size_t)(r0 + 8) * DD + col] =
            make_float2(Ofr[nf][2] * i1, Ofr[nf][3] * i1);
    }
}

// ---------------- layernorm over last dim (D=512), one block per row -------
__global__ __launch_bounds__(256) void layernorm_k(
    const float* __restrict__ in, const float* __restrict__ gamma,
    const float* __restrict__ beta, float* __restrict__ out)
{
    const int row = blockIdx.x;
    const int tid = threadIdx.x;
    const float* xr = in + (size_t)row * DD;

    const float x0 = xr[tid];
    const float x1 = xr[tid + 256];

    __shared__ float wsum[8];
    __shared__ float sval;

    float s = x0 + x1;
#pragma unroll
    for (int off = 16; off; off >>= 1) s += __shfl_xor_sync(0xffffffffu, s, off);
    if ((tid & 31) == 0) wsum[tid >> 5] = s;
    __syncthreads();
    if (tid == 0) {
        float t = 0.f;
#pragma unroll
        for (int i = 0; i < 8; i++) t += wsum[i];
        sval = t * (1.f / DD);
    }
    __syncthreads();
    const float mu = sval;
    __syncthreads();

    const float d0 = x0 - mu, d1 = x1 - mu;
    s = d0 * d0 + d1 * d1;
#pragma unroll
    for (int off = 16; off; off >>= 1) s += __shfl_xor_sync(0xffffffffu, s, off);
    if ((tid & 31) == 0) wsum[tid >> 5] = s;
    __syncthreads();
    if (tid == 0) {
        float t = 0.f;
#pragma unroll
        for (int i = 0; i < 8; i++) t += wsum[i];
        sval = rsqrtf(t * (1.f / DD) + 1e-5f);
    }
    __syncthreads();
    const float rstd = sval;

    out[(size_t)row * DD + tid]       = d0 * rstd * gamma[tid] + beta[tid];
    out[(size_t)row * DD + tid + 256] = d1 * rstd * gamma[tid + 256] + beta[tid + 256];
}

// ---------------- launch --------------------------------------------------
extern "C" void kernel_launch(void* const* d_in, const int* in_sizes, int n_in,
                              void* d_out, int out_size)
{
    const float* x    = (const float*)d_in[0];
    const int*   mask = (const int*)d_in[1];
    const float* Wq   = (const float*)d_in[2];
    const float* Wk   = (const float*)d_in[3];
    const float* Wv   = (const float*)d_in[4];
    const float* Wp   = (const float*)d_in[5];
    const float* W1   = (const float*)d_in[6];
    const float* b1   = (const float*)d_in[7];
    const float* W2   = (const float*)d_in[8];
    const float* b2   = (const float*)d_in[9];
    const float* ln1g = (const float*)d_in[10];
    const float* ln1b = (const float*)d_in[11];
    const float* ln2g = (const float*)d_in[12];
    const float* ln2b = (const float*)d_in[13];
    float* out = (float*)d_out;

    float *q, *k, *v, *ctx, *attres, *h, *ff;
    cudaGetSymbolAddress((void**)&q,      g_q);
    cudaGetSymbolAddress((void**)&k,      g_k);
    cudaGetSymbolAddress((void**)&v,      g_v);
    cudaGetSymbolAddress((void**)&ctx,    g_ctx);
    cudaGetSymbolAddress((void**)&attres, g_attres);
    cudaGetSymbolAddress((void**)&h,      g_h);
    cudaGetSymbolAddress((void**)&ff,     g_ff);

    dim3 g512(DD / 128, MROWS / 128);     // (4, 64)
    dim3 g2048(DFF / 128, MROWS / 128);   // (16, 64)

    // QKV projections
    gemm_h<0><<<g512, 256>>>(x, Wq, nullptr, nullptr, q, MROWS, DD, DD);
    gemm_h<0><<<g512, 256>>>(x, Wk, nullptr, nullptr, k, MROWS, DD, DD);
    gemm_h<0><<<g512, 256>>>(x, Wv, nullptr, nullptr, v, MROWS, DD, DD);

    // attention (tensor-core flash)
    dim3 ga(BB * HH, SS / 128);
    attn_mma<<<ga, 256>>>(q, k, v, mask, ctx);

    // output projection + residual, LN1
    gemm_h<1><<<g512, 256>>>(ctx, Wp, nullptr, x, attres, MROWS, DD, DD);
    layernorm_k<<<MROWS, 256>>>(attres, ln1g, ln1b, h);

    // FFN
    gemm_h<2><<<g2048, 256>>>(h, W1, b1, nullptr, ff, MROWS, DFF, DD);
    gemm_h<3><<<g512, 256>>>(ff, W2, b2, h, attres, MROWS, DD, DFF);
    layernorm_k<<<MROWS, 256>>>(attres, ln2g, ln2b, out);
}